// round 1
// baseline (speedup 1.0000x reference)
#include <cuda_runtime.h>
#include <math.h>

// ---------------- problem constants ----------------
#define BB   8
#define NN   2048
#define MM   2048
#define GG   544          // NUM_GRID = ceil(128*4.2/16)*16
#define RC   8            // RHO_C
#define SC   1024         // SIGMA_CH
#define XMINF (-2.1f)
#define STEPF ((float)(4.2 / 543.0))   // (XMAX-XMIN)/(NUM_GRID-1)

// ---------------- scratch (device globals: no allocation) ----------------
__device__ float g_h[BB * GG * RC];                       // h[b,g,c]
__device__ float g_basis[(size_t)BB * MM * SC];           // basis[b,m,k]

// =====================================================================
// Kernel 1: encode.  One block per (b,g).
// F0[b,g] = sum_n exp(c0*(x-gv)^2) ; F1 = sum_n y*exp(c1*(x-gv)^2)
// then h = sigmoid([F0, F1/(F0+1e-8)] @ enc_W + enc_b) @ rho_W + rho_b
// =====================================================================
__global__ void __launch_bounds__(256) encode_kernel(
    const float* __restrict__ x, const float* __restrict__ y,
    const float* __restrict__ enc_sigma, const float* __restrict__ enc_W,
    const float* __restrict__ enc_b, const float* __restrict__ rho_W,
    const float* __restrict__ rho_b)
{
    int bg = blockIdx.x;
    int b  = bg / GG;
    int g  = bg % GG;
    float gv = XMINF + (float)g * STEPF;

    float s0 = __expf(enc_sigma[0]);  float c0 = -0.5f / (s0 * s0);
    float s1 = __expf(enc_sigma[1]);  float c1 = -0.5f / (s1 * s1);

    const float* xb = x + b * NN;
    const float* yb = y + b * NN;

    float f0 = 0.f, f1 = 0.f;
    for (int n = threadIdx.x; n < NN; n += 256) {
        float dx = xb[n] - gv;
        float d  = dx * dx;
        f0 += __expf(c0 * d);
        f1 += yb[n] * __expf(c1 * d);
    }
    // warp reduce
    for (int off = 16; off; off >>= 1) {
        f0 += __shfl_xor_sync(0xffffffffu, f0, off);
        f1 += __shfl_xor_sync(0xffffffffu, f1, off);
    }
    __shared__ float r0[8], r1[8];
    int warp = threadIdx.x >> 5, lane = threadIdx.x & 31;
    if (lane == 0) { r0[warp] = f0; r1[warp] = f1; }
    __syncthreads();

    if (threadIdx.x == 0) {
        float den = 0.f, conv = 0.f;
        #pragma unroll
        for (int w = 0; w < 8; w++) { den += r0[w]; conv += r1[w]; }
        float F0 = den;
        float F1 = conv / (den + 1e-8f);

        float hh[RC];
        #pragma unroll
        for (int c = 0; c < RC; c++) {
            float z = F0 * enc_W[c] + F1 * enc_W[RC + c] + enc_b[c];
            hh[c] = 1.f / (1.f + __expf(-z));
        }
        #pragma unroll
        for (int c = 0; c < RC; c++) {
            float acc = rho_b[c];
            #pragma unroll
            for (int j = 0; j < RC; j++) acc += hh[j] * rho_W[j * RC + c];
            g_h[bg * RC + c] = acc;
        }
    }
}

// =====================================================================
// Kernel 2: project.  One warp per (b,m): 8 warps (8 m's) per block.
// pm[c] = sum_g h[b,g,c]*exp(mc[c]*(gv-xo)^2)   (mean path)
// ps[c] = sum_g h[b,g,c]*exp(sc[c]*(gv-xo)^2)   (sigma path)
// mean[b,m]      = pm @ mean_W + mean_b
// basis[b,m,k]   = ps @ sig_W[:,k] + sig_b[k]
// =====================================================================
__global__ void __launch_bounds__(256) project_kernel(
    const float* __restrict__ x_out,
    const float* __restrict__ mean_sigma, const float* __restrict__ mean_W,
    const float* __restrict__ mean_b,
    const float* __restrict__ sig_sigma, const float* __restrict__ sig_W,
    const float* __restrict__ sig_b,
    float* __restrict__ mean_out)
{
    __shared__ float h_sh[RC * GG];    // layout [c][g] -> conflict-free over g

    int b  = blockIdx.x >> 8;          // 256 blocks per batch
    int m0 = (blockIdx.x & 255) * 8;
    int tid = threadIdx.x;

    // load + transpose h for this batch
    for (int i = tid; i < RC * GG; i += 256) {
        int g = i / RC, c = i % RC;
        h_sh[c * GG + g] = g_h[(b * GG + g) * RC + c];
    }
    __syncthreads();

    int warp = tid >> 5, lane = tid & 31;
    int m = m0 + warp;
    float xo = x_out[b * MM + m];

    float mc[RC], scf[RC];
    #pragma unroll
    for (int c = 0; c < RC; c++) {
        float s = __expf(mean_sigma[c]); mc[c]  = -0.5f / (s * s);
        s       = __expf(sig_sigma[c]);  scf[c] = -0.5f / (s * s);
    }

    float pm[RC] = {}, ps[RC] = {};
    for (int g = lane; g < GG; g += 32) {
        float gv = XMINF + (float)g * STEPF;
        float dd = gv - xo; dd *= dd;
        #pragma unroll
        for (int c = 0; c < RC; c++) {
            float hv = h_sh[c * GG + g];
            pm[c] += hv * __expf(mc[c]  * dd);
            ps[c] += hv * __expf(scf[c] * dd);
        }
    }
    #pragma unroll
    for (int c = 0; c < RC; c++) {
        for (int off = 16; off; off >>= 1) {
            pm[c] += __shfl_xor_sync(0xffffffffu, pm[c], off);
            ps[c] += __shfl_xor_sync(0xffffffffu, ps[c], off);
        }
    }

    if (lane == 0) {
        float mv = mean_b[0];
        #pragma unroll
        for (int c = 0; c < RC; c++) mv += pm[c] * mean_W[c];
        mean_out[b * MM + m] = mv;
    }

    float* bo = g_basis + ((size_t)(b * MM + m)) * SC;
    for (int k = lane; k < SC; k += 32) {
        float acc = sig_b[k];
        #pragma unroll
        for (int c = 0; c < RC; c++) acc += ps[c] * sig_W[c * SC + k];
        bo[k] = acc;
    }
}

// =====================================================================
// Kernel 3: SYRK  cov[b] = basis[b] @ basis[b]^T + exp(noise)*I
// 128x128 tile, 256 threads, 8x8 per thread, K-tile 16.
// Only upper-triangular tiles (tm<=tn) computed; mirror via vectorized stores.
// =====================================================================
__global__ void __launch_bounds__(256) syrk_kernel(
    float* __restrict__ cov, const float* __restrict__ noise_scale)
{
    int b = blockIdx.y;
    int t = blockIdx.x;                 // 0..135 triangular tile index
    int tn = (int)((sqrtf(8.0f * (float)t + 1.0f) - 1.0f) * 0.5f);
    while (tn * (tn + 1) / 2 > t) tn--;
    while ((tn + 1) * (tn + 2) / 2 <= t) tn++;
    int tm = t - tn * (tn + 1) / 2;

    const float* A = g_basis + (size_t)b * MM * SC;
    float* C = cov + (size_t)b * MM * MM;

    __shared__ __align__(16) float As[16][132];   // +4 pad: keeps 16B align, reduces STS conflicts
    __shared__ __align__(16) float Bs[16][132];

    int tid = threadIdx.x;
    int tx = tid & 15, ty = tid >> 4;

    int rowBase = tm * 128;
    int colBase = tn * 128;

    float acc[8][8] = {};

    for (int k0 = 0; k0 < SC; k0 += 16) {
        #pragma unroll
        for (int l = 0; l < 2; l++) {
            int idx = tid + l * 256;      // 0..511
            int r   = idx >> 2;           // 0..127
            int c4  = idx & 3;            // 0..3 (covers 16 k as 4 float4)
            float4 va = *(const float4*)(A + (size_t)(rowBase + r) * SC + k0 + c4 * 4);
            As[c4 * 4 + 0][r] = va.x; As[c4 * 4 + 1][r] = va.y;
            As[c4 * 4 + 2][r] = va.z; As[c4 * 4 + 3][r] = va.w;
            float4 vb = *(const float4*)(A + (size_t)(colBase + r) * SC + k0 + c4 * 4);
            Bs[c4 * 4 + 0][r] = vb.x; Bs[c4 * 4 + 1][r] = vb.y;
            Bs[c4 * 4 + 2][r] = vb.z; Bs[c4 * 4 + 3][r] = vb.w;
        }
        __syncthreads();

        #pragma unroll
        for (int kk = 0; kk < 16; kk++) {
            float a[8], bv[8];
            *(float4*)(a)      = *(const float4*)&As[kk][ty * 8];
            *(float4*)(a + 4)  = *(const float4*)&As[kk][ty * 8 + 4];
            *(float4*)(bv)     = *(const float4*)&Bs[kk][tx * 8];
            *(float4*)(bv + 4) = *(const float4*)&Bs[kk][tx * 8 + 4];
            #pragma unroll
            for (int i = 0; i < 8; i++)
                #pragma unroll
                for (int j = 0; j < 8; j++)
                    acc[i][j] = fmaf(a[i], bv[j], acc[i][j]);
        }
        __syncthreads();
    }

    float noisev = __expf(noise_scale[0]);

    // diagonal-tile noise injection (only possible when tm==tn and ty==tx)
    if (tm == tn && ty == tx) {
        #pragma unroll
        for (int i = 0; i < 8; i++) acc[i][i] += noisev;
    }

    // primary write: C[row][col], vectorized
    #pragma unroll
    for (int i = 0; i < 8; i++) {
        int r = rowBase + ty * 8 + i;
        float4* dst = (float4*)(C + (size_t)r * MM + colBase + tx * 8);
        dst[0] = make_float4(acc[i][0], acc[i][1], acc[i][2], acc[i][3]);
        dst[1] = make_float4(acc[i][4], acc[i][5], acc[i][6], acc[i][7]);
    }

    // mirror write: C[col][row] (r < col always when tm<tn, so no noise here)
    if (tm != tn) {
        #pragma unroll
        for (int j = 0; j < 8; j++) {
            int cI = colBase + tx * 8 + j;
            float4* dst = (float4*)(C + (size_t)cI * MM + rowBase + ty * 8);
            dst[0] = make_float4(acc[0][j], acc[1][j], acc[2][j], acc[3][j]);
            dst[1] = make_float4(acc[4][j], acc[5][j], acc[6][j], acc[7][j]);
        }
    }
}

// =====================================================================
// launch
// =====================================================================
extern "C" void kernel_launch(void* const* d_in, const int* in_sizes, int n_in,
                              void* d_out, int out_size)
{
    const float* x          = (const float*)d_in[0];
    const float* y          = (const float*)d_in[1];
    const float* x_out      = (const float*)d_in[2];
    const float* enc_sigma  = (const float*)d_in[3];
    const float* enc_W      = (const float*)d_in[4];
    const float* enc_b      = (const float*)d_in[5];
    const float* rho_W      = (const float*)d_in[6];
    const float* rho_b      = (const float*)d_in[7];
    const float* mean_sigma = (const float*)d_in[8];
    const float* mean_W     = (const float*)d_in[9];
    const float* mean_b     = (const float*)d_in[10];
    const float* sig_sigma  = (const float*)d_in[11];
    const float* sig_W      = (const float*)d_in[12];
    const float* sig_b      = (const float*)d_in[13];
    const float* noise      = (const float*)d_in[14];

    float* out      = (float*)d_out;
    float* mean_out = out;                    // (8, 2048, 1)
    float* cov_out  = out + BB * MM;          // (8, 2048, 2048)

    encode_kernel<<<BB * GG, 256>>>(x, y, enc_sigma, enc_W, enc_b, rho_W, rho_b);

    project_kernel<<<BB * 256, 256>>>(x_out, mean_sigma, mean_W, mean_b,
                                      sig_sigma, sig_W, sig_b, mean_out);

    dim3 sgrid(136, BB);
    syrk_kernel<<<sgrid, 256>>>(cov_out, noise);
}

// round 2
// speedup vs baseline: 7.2468x; 7.2468x over previous
#include <cuda_runtime.h>
#include <math.h>

// ---------------- problem constants ----------------
#define BB   8
#define NN   2048
#define MM   2048
#define GG   544          // NUM_GRID
#define RC   8            // RHO_C
#define SC   1024         // SIGMA_CH
#define XMINF (-2.1f)
#define STEPF ((float)(4.2 / 543.0))   // (XMAX-XMIN)/(NUM_GRID-1)

// ---------------- scratch (device globals: no allocation) ----------------
__device__ float g_h[BB * GG * RC];          // h[b,g,c]
__device__ float g_P[BB * MM * RC];          // ps[b,m,c]
__device__ float g_Q[BB * MM * RC];          // (G @ ps)[b,m,c]
__device__ float g_u[BB * MM];               // ps . (W b)
__device__ float g_G[RC * RC];               // sig_W sig_W^T
__device__ float g_wb[RC];                   // sig_W @ sig_b
__device__ float g_s[1];                     // sig_b . sig_b

// =====================================================================
// Kernel 0: gram.  G = sig_W sig_W^T (8x8), wb = sig_W @ sig_b, s = b.b
// one block, 256 threads.
// =====================================================================
__global__ void __launch_bounds__(256) gram_kernel(
    const float* __restrict__ sig_W, const float* __restrict__ sig_b)
{
    int tid = threadIdx.x, warp = tid >> 5, lane = tid & 31;

    // 64 (i,j) pairs: warp w handles pairs 8w .. 8w+7
    for (int p = warp * 8; p < warp * 8 + 8; p++) {
        int i = p >> 3, j = p & 7;
        float acc = 0.f;
        for (int k = lane; k < SC; k += 32)
            acc += sig_W[i * SC + k] * sig_W[j * SC + k];
        for (int off = 16; off; off >>= 1)
            acc += __shfl_xor_sync(0xffffffffu, acc, off);
        if (lane == 0) g_G[p] = acc;
    }
    // wb[w] by warp w
    {
        float acc = 0.f;
        for (int k = lane; k < SC; k += 32)
            acc += sig_W[warp * SC + k] * sig_b[k];
        for (int off = 16; off; off >>= 1)
            acc += __shfl_xor_sync(0xffffffffu, acc, off);
        if (lane == 0) g_wb[warp] = acc;
    }
    // s by warp 0
    if (warp == 0) {
        float acc = 0.f;
        for (int k = lane; k < SC; k += 32)
            acc += sig_b[k] * sig_b[k];
        for (int off = 16; off; off >>= 1)
            acc += __shfl_xor_sync(0xffffffffu, acc, off);
        if (lane == 0) g_s[0] = acc;
    }
}

// =====================================================================
// Kernel 1: encode.  One block per (b,g).
// =====================================================================
__global__ void __launch_bounds__(256) encode_kernel(
    const float* __restrict__ x, const float* __restrict__ y,
    const float* __restrict__ enc_sigma, const float* __restrict__ enc_W,
    const float* __restrict__ enc_b, const float* __restrict__ rho_W,
    const float* __restrict__ rho_b)
{
    int bg = blockIdx.x;
    int b  = bg / GG;
    int g  = bg % GG;
    float gv = XMINF + (float)g * STEPF;

    float es0 = enc_sigma[0], es1 = enc_sigma[1];
    float s0 = __expf(es0);  float c0 = -0.5f / (s0 * s0);
    float s1 = __expf(es1);  float c1 = -0.5f / (s1 * s1);
    bool same = (es0 == es1);

    const float* xb = x + b * NN;
    const float* yb = y + b * NN;

    float f0 = 0.f, f1 = 0.f;
    if (same) {
        for (int n = threadIdx.x; n < NN; n += 256) {
            float dx = xb[n] - gv;
            float e  = __expf(c0 * dx * dx);
            f0 += e;
            f1 += yb[n] * e;
        }
    } else {
        for (int n = threadIdx.x; n < NN; n += 256) {
            float dx = xb[n] - gv;
            float d  = dx * dx;
            f0 += __expf(c0 * d);
            f1 += yb[n] * __expf(c1 * d);
        }
    }
    for (int off = 16; off; off >>= 1) {
        f0 += __shfl_xor_sync(0xffffffffu, f0, off);
        f1 += __shfl_xor_sync(0xffffffffu, f1, off);
    }
    __shared__ float r0[8], r1[8];
    int warp = threadIdx.x >> 5, lane = threadIdx.x & 31;
    if (lane == 0) { r0[warp] = f0; r1[warp] = f1; }
    __syncthreads();

    if (threadIdx.x == 0) {
        float den = 0.f, conv = 0.f;
        #pragma unroll
        for (int w = 0; w < 8; w++) { den += r0[w]; conv += r1[w]; }
        float F0 = den;
        float F1 = conv / (den + 1e-8f);

        float hh[RC];
        #pragma unroll
        for (int c = 0; c < RC; c++) {
            float z = F0 * enc_W[c] + F1 * enc_W[RC + c] + enc_b[c];
            hh[c] = 1.f / (1.f + __expf(-z));
        }
        #pragma unroll
        for (int c = 0; c < RC; c++) {
            float acc = rho_b[c];
            #pragma unroll
            for (int j = 0; j < RC; j++) acc += hh[j] * rho_W[j * RC + c];
            g_h[bg * RC + c] = acc;
        }
    }
}

// =====================================================================
// Kernel 2: project.  One warp per (b,m).
// pm[c] = sum_g h[b,g,c]*exp(mc[c]*dd); ps likewise with sig coeffs.
// mean = pm @ mean_W + mean_b;  P=ps, Q=G@ps, u=ps.wb stored for cov.
// =====================================================================
__global__ void __launch_bounds__(256) project_kernel(
    const float* __restrict__ x_out,
    const float* __restrict__ mean_sigma, const float* __restrict__ mean_W,
    const float* __restrict__ mean_b,
    const float* __restrict__ sig_sigma,
    float* __restrict__ mean_out)
{
    __shared__ float h_sh[RC * GG];    // [c][g]

    int b  = blockIdx.x >> 8;
    int m0 = (blockIdx.x & 255) * 8;
    int tid = threadIdx.x;

    for (int i = tid; i < RC * GG; i += 256) {
        int g = i / RC, c = i % RC;
        h_sh[c * GG + g] = g_h[(b * GG + g) * RC + c];
    }
    __syncthreads();

    int warp = tid >> 5, lane = tid & 31;
    int m = m0 + warp;
    float xo = x_out[b * MM + m];

    float ms0 = mean_sigma[0];
    bool uni = true;
    float mc[RC], scf[RC];
    #pragma unroll
    for (int c = 0; c < RC; c++) {
        float msc = mean_sigma[c], ssc = sig_sigma[c];
        uni = uni && (msc == ms0) && (ssc == ms0);
        float s = __expf(msc); mc[c]  = -0.5f / (s * s);
        s       = __expf(ssc); scf[c] = -0.5f / (s * s);
    }

    float pm[RC] = {}, ps[RC] = {};
    if (uni) {
        float coef = mc[0];
        for (int g = lane; g < GG; g += 32) {
            float gv = XMINF + (float)g * STEPF;
            float dd = gv - xo; dd *= dd;
            float e = __expf(coef * dd);
            #pragma unroll
            for (int c = 0; c < RC; c++)
                pm[c] += h_sh[c * GG + g] * e;
        }
        #pragma unroll
        for (int c = 0; c < RC; c++) ps[c] = pm[c];
    } else {
        for (int g = lane; g < GG; g += 32) {
            float gv = XMINF + (float)g * STEPF;
            float dd = gv - xo; dd *= dd;
            #pragma unroll
            for (int c = 0; c < RC; c++) {
                float hv = h_sh[c * GG + g];
                pm[c] += hv * __expf(mc[c]  * dd);
                ps[c] += hv * __expf(scf[c] * dd);
            }
        }
    }
    #pragma unroll
    for (int c = 0; c < RC; c++) {
        for (int off = 16; off; off >>= 1) {
            pm[c] += __shfl_xor_sync(0xffffffffu, pm[c], off);
            ps[c] += __shfl_xor_sync(0xffffffffu, ps[c], off);
        }
    }

    if (lane == 0) {
        float mv = mean_b[0];
        #pragma unroll
        for (int c = 0; c < RC; c++) mv += pm[c] * mean_W[c];
        mean_out[b * MM + m] = mv;

        size_t base = (size_t)(b * MM + m) * RC;
        float uacc = 0.f;
        #pragma unroll
        for (int c = 0; c < RC; c++) {
            g_P[base + c] = ps[c];
            uacc += ps[c] * g_wb[c];
            float qc = 0.f;
            #pragma unroll
            for (int j = 0; j < RC; j++) qc += g_G[c * RC + j] * ps[j];
            g_Q[base + c] = qc;
        }
        g_u[b * MM + m] = uacc;
    }
}

// =====================================================================
// Kernel 3: cov[b,m,n] = Q[b,m].P[b,n] + u[m] + u[n] + s (+ noise on diag)
// 128x128 tile per block, 256 threads (16x16), 8x8 per thread. Store-bound.
// =====================================================================
__global__ void __launch_bounds__(256) cov_kernel(
    float* __restrict__ cov, const float* __restrict__ noise_scale)
{
    int b  = blockIdx.y;
    int tm = blockIdx.x >> 4;
    int tn = blockIdx.x & 15;

    __shared__ float Qs[128][RC + 1];
    __shared__ float Ps[128][RC + 1];
    __shared__ float Um[128], Un[128];

    int tid = threadIdx.x;
    int rowBase = tm * 128, colBase = tn * 128;

    for (int i = tid; i < 128 * RC; i += 256) {
        int r = i >> 3, c = i & 7;
        Qs[r][c] = g_Q[(size_t)(b * MM + rowBase + r) * RC + c];
        Ps[r][c] = g_P[(size_t)(b * MM + colBase + r) * RC + c];
    }
    if (tid < 128) {
        Um[tid] = g_u[b * MM + rowBase + tid];
        Un[tid] = g_u[b * MM + colBase + tid];
    }
    __syncthreads();

    int tx = tid & 15, ty = tid >> 4;

    float acc[8][8] = {};
    #pragma unroll
    for (int k = 0; k < RC; k++) {
        float q[8], p[8];
        #pragma unroll
        for (int i = 0; i < 8; i++) q[i] = Qs[ty * 8 + i][k];
        #pragma unroll
        for (int j = 0; j < 8; j++) p[j] = Ps[tx * 8 + j][k];
        #pragma unroll
        for (int i = 0; i < 8; i++)
            #pragma unroll
            for (int j = 0; j < 8; j++)
                acc[i][j] = fmaf(q[i], p[j], acc[i][j]);
    }

    float sconst = g_s[0];
    float noisev = __expf(noise_scale[0]);

    #pragma unroll
    for (int i = 0; i < 8; i++) {
        float um = Um[ty * 8 + i] + sconst;
        #pragma unroll
        for (int j = 0; j < 8; j++)
            acc[i][j] += um + Un[tx * 8 + j];
    }
    if (tm == tn && ty == tx) {
        #pragma unroll
        for (int i = 0; i < 8; i++) acc[i][i] += noisev;
    }

    float* C = cov + (size_t)b * MM * MM;
    #pragma unroll
    for (int i = 0; i < 8; i++) {
        int r = rowBase + ty * 8 + i;
        float4* dst = (float4*)(C + (size_t)r * MM + colBase + tx * 8);
        dst[0] = make_float4(acc[i][0], acc[i][1], acc[i][2], acc[i][3]);
        dst[1] = make_float4(acc[i][4], acc[i][5], acc[i][6], acc[i][7]);
    }
}

// =====================================================================
// launch
// =====================================================================
extern "C" void kernel_launch(void* const* d_in, const int* in_sizes, int n_in,
                              void* d_out, int out_size)
{
    const float* x          = (const float*)d_in[0];
    const float* y          = (const float*)d_in[1];
    const float* x_out      = (const float*)d_in[2];
    const float* enc_sigma  = (const float*)d_in[3];
    const float* enc_W      = (const float*)d_in[4];
    const float* enc_b      = (const float*)d_in[5];
    const float* rho_W      = (const float*)d_in[6];
    const float* rho_b      = (const float*)d_in[7];
    const float* mean_sigma = (const float*)d_in[8];
    const float* mean_W     = (const float*)d_in[9];
    const float* mean_b     = (const float*)d_in[10];
    const float* sig_sigma  = (const float*)d_in[11];
    const float* sig_W      = (const float*)d_in[12];
    const float* sig_b      = (const float*)d_in[13];
    const float* noise      = (const float*)d_in[14];

    float* out      = (float*)d_out;
    float* mean_out = out;                    // (8, 2048, 1)
    float* cov_out  = out + BB * MM;          // (8, 2048, 2048)

    gram_kernel<<<1, 256>>>(sig_W, sig_b);

    encode_kernel<<<BB * GG, 256>>>(x, y, enc_sigma, enc_W, enc_b, rho_W, rho_b);

    project_kernel<<<BB * 256, 256>>>(x_out, mean_sigma, mean_W, mean_b,
                                      sig_sigma, mean_out);

    dim3 cgrid(256, BB);
    cov_kernel<<<cgrid, 256>>>(cov_out, noise);
}

// round 3
// speedup vs baseline: 10.6501x; 1.4696x over previous
#include <cuda_runtime.h>
#include <math.h>

// ---------------- problem constants ----------------
#define BB   8
#define NN   2048
#define MM   2048
#define GG   544          // NUM_GRID
#define RC   8            // RHO_C
#define SC   1024         // SIGMA_CH
#define XMINF (-2.1f)
#define STEPF ((float)(4.2 / 543.0))

// ---------------- scratch (device globals) ----------------
__device__ float g_h[BB * RC * GG];          // h transposed: [b][c][g]
__device__ float g_P[BB * MM * RC];          // ps[b,m,c]
__device__ float g_Q[BB * MM * RC];          // (G @ ps)[b,m,c]
__device__ float g_u[BB * MM];               // ps . (W b)
__device__ float g_G[RC * RC];               // sig_W sig_W^T
__device__ float g_wb[RC];                   // sig_W @ sig_b
__device__ float g_s[1];                     // sig_b . sig_b

// =====================================================================
// Kernel 0: gram.  G = sig_W sig_W^T (8x8), wb = sig_W @ sig_b, s = b.b
// =====================================================================
__global__ void __launch_bounds__(256) gram_kernel(
    const float* __restrict__ sig_W, const float* __restrict__ sig_b)
{
    int tid = threadIdx.x, warp = tid >> 5, lane = tid & 31;

    for (int p = warp * 8; p < warp * 8 + 8; p++) {
        int i = p >> 3, j = p & 7;
        float acc = 0.f;
        for (int k = lane; k < SC; k += 32)
            acc += sig_W[i * SC + k] * sig_W[j * SC + k];
        for (int off = 16; off; off >>= 1)
            acc += __shfl_xor_sync(0xffffffffu, acc, off);
        if (lane == 0) g_G[p] = acc;
    }
    {
        float acc = 0.f;
        for (int k = lane; k < SC; k += 32)
            acc += sig_W[warp * SC + k] * sig_b[k];
        for (int off = 16; off; off >>= 1)
            acc += __shfl_xor_sync(0xffffffffu, acc, off);
        if (lane == 0) g_wb[warp] = acc;
    }
    if (warp == 0) {
        float acc = 0.f;
        for (int k = lane; k < SC; k += 32)
            acc += sig_b[k] * sig_b[k];
        for (int off = 16; off; off >>= 1)
            acc += __shfl_xor_sync(0xffffffffu, acc, off);
        if (lane == 0) g_s[0] = acc;
    }
}

// =====================================================================
// Kernel 1: encode.  One WARP per (b,g); 8 warps/block; float4 loads.
// Output written transposed: g_h[b][c][g].
// =====================================================================
__global__ void __launch_bounds__(256) encode_kernel(
    const float* __restrict__ x, const float* __restrict__ y,
    const float* __restrict__ enc_sigma, const float* __restrict__ enc_W,
    const float* __restrict__ enc_b, const float* __restrict__ rho_W,
    const float* __restrict__ rho_b)
{
    int warp = threadIdx.x >> 5, lane = threadIdx.x & 31;
    int bg = blockIdx.x * 8 + warp;
    int b  = bg / GG;
    int g  = bg % GG;
    float gv = XMINF + (float)g * STEPF;

    float es0 = enc_sigma[0], es1 = enc_sigma[1];
    float s0 = __expf(es0);  float c0 = -0.5f / (s0 * s0);
    float s1 = __expf(es1);  float c1 = -0.5f / (s1 * s1);
    bool same = (es0 == es1);

    const float4* xb = (const float4*)(x + b * NN);
    const float4* yb = (const float4*)(y + b * NN);

    float f0 = 0.f, f1 = 0.f;
    if (same) {
        #pragma unroll 4
        for (int n = lane; n < NN / 4; n += 32) {
            float4 xv = xb[n], yv = yb[n];
            float dx;
            dx = xv.x - gv; { float e = __expf(c0 * dx * dx); f0 += e; f1 += yv.x * e; }
            dx = xv.y - gv; { float e = __expf(c0 * dx * dx); f0 += e; f1 += yv.y * e; }
            dx = xv.z - gv; { float e = __expf(c0 * dx * dx); f0 += e; f1 += yv.z * e; }
            dx = xv.w - gv; { float e = __expf(c0 * dx * dx); f0 += e; f1 += yv.w * e; }
        }
    } else {
        #pragma unroll 4
        for (int n = lane; n < NN / 4; n += 32) {
            float4 xv = xb[n], yv = yb[n];
            float dx, d;
            dx = xv.x - gv; d = dx * dx; f0 += __expf(c0 * d); f1 += yv.x * __expf(c1 * d);
            dx = xv.y - gv; d = dx * dx; f0 += __expf(c0 * d); f1 += yv.y * __expf(c1 * d);
            dx = xv.z - gv; d = dx * dx; f0 += __expf(c0 * d); f1 += yv.z * __expf(c1 * d);
            dx = xv.w - gv; d = dx * dx; f0 += __expf(c0 * d); f1 += yv.w * __expf(c1 * d);
        }
    }
    for (int off = 16; off; off >>= 1) {
        f0 += __shfl_xor_sync(0xffffffffu, f0, off);
        f1 += __shfl_xor_sync(0xffffffffu, f1, off);
    }
    // all lanes now hold the full sums; lanes 0-7 finish in parallel
    float F0 = f0;
    float F1 = f1 / (f0 + 1e-8f);

    // every lane computes all hh (cheap, avoids shuffles)
    float hh[RC];
    #pragma unroll
    for (int c = 0; c < RC; c++) {
        float z = F0 * enc_W[c] + F1 * enc_W[RC + c] + enc_b[c];
        hh[c] = 1.f / (1.f + __expf(-z));
    }
    if (lane < RC) {
        int c = lane;
        float acc = rho_b[c];
        #pragma unroll
        for (int j = 0; j < RC; j++) acc += hh[j] * rho_W[j * RC + c];
        g_h[(b * RC + c) * GG + g] = acc;   // transposed layout
    }
}

// =====================================================================
// Kernel 2: project.  One warp per (b,m); 8 warps/block.
// =====================================================================
__global__ void __launch_bounds__(256) project_kernel(
    const float* __restrict__ x_out,
    const float* __restrict__ mean_sigma, const float* __restrict__ mean_W,
    const float* __restrict__ mean_b,
    const float* __restrict__ sig_sigma,
    float* __restrict__ mean_out)
{
    __shared__ float h_sh[RC * GG];    // [c][g], same layout as g_h slice

    int b  = blockIdx.x >> 8;
    int m0 = (blockIdx.x & 255) * 8;
    int tid = threadIdx.x;

    // coalesced copy of this batch's transposed h
    for (int i = tid; i < RC * GG; i += 256)
        h_sh[i] = g_h[b * RC * GG + i];
    __syncthreads();

    int warp = tid >> 5, lane = tid & 31;
    int m = m0 + warp;
    float xo = x_out[b * MM + m];

    float ms0 = mean_sigma[0];
    bool uni = true;
    float mc[RC], scf[RC];
    #pragma unroll
    for (int c = 0; c < RC; c++) {
        float msc = mean_sigma[c], ssc = sig_sigma[c];
        uni = uni && (msc == ms0) && (ssc == ms0);
        float s = __expf(msc); mc[c]  = -0.5f / (s * s);
        s       = __expf(ssc); scf[c] = -0.5f / (s * s);
    }

    float pm[RC] = {}, ps[RC] = {};
    if (uni) {
        float coef = mc[0];
        #pragma unroll 1
        for (int g = lane; g < GG; g += 32) {
            float gv = XMINF + (float)g * STEPF;
            float dd = gv - xo; dd *= dd;
            float e = __expf(coef * dd);
            #pragma unroll
            for (int c = 0; c < RC; c++)
                pm[c] += h_sh[c * GG + g] * e;
        }
        #pragma unroll
        for (int c = 0; c < RC; c++) ps[c] = pm[c];
    } else {
        #pragma unroll 1
        for (int g = lane; g < GG; g += 32) {
            float gv = XMINF + (float)g * STEPF;
            float dd = gv - xo; dd *= dd;
            #pragma unroll
            for (int c = 0; c < RC; c++) {
                float hv = h_sh[c * GG + g];
                pm[c] += hv * __expf(mc[c]  * dd);
                ps[c] += hv * __expf(scf[c] * dd);
            }
        }
    }
    #pragma unroll
    for (int c = 0; c < RC; c++) {
        for (int off = 16; off; off >>= 1) {
            pm[c] += __shfl_xor_sync(0xffffffffu, pm[c], off);
            ps[c] += __shfl_xor_sync(0xffffffffu, ps[c], off);
        }
    }
    // all lanes hold full pm/ps now — parallel epilogue
    size_t base = (size_t)(b * MM + m) * RC;
    if (lane < RC) {
        int c = lane;
        g_P[base + c] = ps[c];
        float qc = 0.f;
        #pragma unroll
        for (int j = 0; j < RC; j++) qc = fmaf(g_G[c * RC + j], ps[j], qc);
        g_Q[base + c] = qc;
    } else if (lane == 8) {
        float uacc = 0.f;
        #pragma unroll
        for (int c = 0; c < RC; c++) uacc = fmaf(ps[c], g_wb[c], uacc);
        g_u[b * MM + m] = uacc;
    } else if (lane == 9) {
        float mv = mean_b[0];
        #pragma unroll
        for (int c = 0; c < RC; c++) mv = fmaf(pm[c], mean_W[c], mv);
        mean_out[b * MM + m] = mv;
    }
}

// =====================================================================
// Kernel 3: cov[b,m,n] = Q[b,m].P[b,n] + u[m] + u[n] + s (+noise diag)
// 64x64 tile per block, 256 threads (16x16), 4x4 per thread.
// =====================================================================
__global__ void __launch_bounds__(256) cov_kernel(
    float* __restrict__ cov, const float* __restrict__ noise_scale)
{
    int b  = blockIdx.y;
    int tm = blockIdx.x >> 5;      // 32 row tiles
    int tn = blockIdx.x & 31;      // 32 col tiles

    __shared__ float Qs[64][RC + 1];
    __shared__ float Ps[64][RC + 1];
    __shared__ float Um[64], Un[64];

    int tid = threadIdx.x;
    int rowBase = tm * 64, colBase = tn * 64;

    // 64*8 = 512 elements each -> 2 per thread
    for (int i = tid; i < 64 * RC; i += 256) {
        int r = i >> 3, c = i & 7;
        Qs[r][c] = g_Q[(size_t)(b * MM + rowBase + r) * RC + c];
        Ps[r][c] = g_P[(size_t)(b * MM + colBase + r) * RC + c];
    }
    if (tid < 64)        Um[tid]      = g_u[b * MM + rowBase + tid];
    else if (tid < 128)  Un[tid - 64] = g_u[b * MM + colBase + tid - 64];
    __syncthreads();

    int tx = tid & 15, ty = tid >> 4;

    float acc[4][4] = {};
    #pragma unroll
    for (int k = 0; k < RC; k++) {
        float q[4], p[4];
        #pragma unroll
        for (int i = 0; i < 4; i++) q[i] = Qs[ty * 4 + i][k];
        #pragma unroll
        for (int j = 0; j < 4; j++) p[j] = Ps[tx * 4 + j][k];
        #pragma unroll
        for (int i = 0; i < 4; i++)
            #pragma unroll
            for (int j = 0; j < 4; j++)
                acc[i][j] = fmaf(q[i], p[j], acc[i][j]);
    }

    float sconst = g_s[0];
    float noisev = __expf(noise_scale[0]);

    #pragma unroll
    for (int i = 0; i < 4; i++) {
        float um = Um[ty * 4 + i] + sconst;
        #pragma unroll
        for (int j = 0; j < 4; j++)
            acc[i][j] += um + Un[tx * 4 + j];
    }
    if (tm == tn && ty == tx) {
        #pragma unroll
        for (int i = 0; i < 4; i++) acc[i][i] += noisev;
    }

    float* C = cov + (size_t)b * MM * MM;
    #pragma unroll
    for (int i = 0; i < 4; i++) {
        int r = rowBase + ty * 4 + i;
        *(float4*)(C + (size_t)r * MM + colBase + tx * 4) =
            make_float4(acc[i][0], acc[i][1], acc[i][2], acc[i][3]);
    }
}

// =====================================================================
// launch
// =====================================================================
extern "C" void kernel_launch(void* const* d_in, const int* in_sizes, int n_in,
                              void* d_out, int out_size)
{
    const float* x          = (const float*)d_in[0];
    const float* y          = (const float*)d_in[1];
    const float* x_out      = (const float*)d_in[2];
    const float* enc_sigma  = (const float*)d_in[3];
    const float* enc_W      = (const float*)d_in[4];
    const float* enc_b      = (const float*)d_in[5];
    const float* rho_W      = (const float*)d_in[6];
    const float* rho_b      = (const float*)d_in[7];
    const float* mean_sigma = (const float*)d_in[8];
    const float* mean_W     = (const float*)d_in[9];
    const float* mean_b     = (const float*)d_in[10];
    const float* sig_sigma  = (const float*)d_in[11];
    const float* sig_W      = (const float*)d_in[12];
    const float* sig_b      = (const float*)d_in[13];
    const float* noise      = (const float*)d_in[14];

    float* out      = (float*)d_out;
    float* mean_out = out;                    // (8, 2048, 1)
    float* cov_out  = out + BB * MM;          // (8, 2048, 2048)

    gram_kernel<<<1, 256>>>(sig_W, sig_b);

    encode_kernel<<<BB * GG / 8, 256>>>(x, y, enc_sigma, enc_W, enc_b, rho_W, rho_b);

    project_kernel<<<BB * 256, 256>>>(x_out, mean_sigma, mean_W, mean_b,
                                      sig_sigma, mean_out);

    dim3 cgrid(1024, BB);   // 32x32 tiles of 64x64
    cov_kernel<<<cgrid, 256>>>(cov_out, noise);
}

// round 4
// speedup vs baseline: 13.6909x; 1.2855x over previous
#include <cuda_runtime.h>
#include <math.h>

// ---------------- problem constants ----------------
#define BB   8
#define NN   2048
#define MM   2048
#define GG   544          // NUM_GRID
#define RC   8            // RHO_C
#define SC   1024         // SIGMA_CH
#define XMINF (-2.1f)
#define STEPF ((float)(4.2 / 543.0))

// ---------------- scratch (device globals) ----------------
__device__ float g_h[BB * RC * GG];          // h transposed: [b][c][g]
__device__ float g_P[BB * MM * RC];          // ps[b,m,c]
__device__ float g_Q[BB * MM * RC];          // (G @ ps)[b,m,c]
__device__ float g_u[BB * MM];               // ps . (W b)
__device__ float g_G[RC * RC];               // sig_W sig_W^T
__device__ float g_wb[RC];                   // sig_W @ sig_b
__device__ float g_s[1];                     // sig_b . sig_b

// ---------------- packed f32x2 helpers (Blackwell) ----------------
#define FMA_F32X2(d, a, b, c) \
    asm("fma.rn.f32x2 %0, %1, %2, %3;" : "=l"(d) : "l"(a), "l"(b), "l"(c))
#define UNPACK_F32X2(lo, hi, v) \
    asm("mov.b64 {%0, %1}, %2;" : "=f"(lo), "=f"(hi) : "l"(v))

// =====================================================================
// Kernel 1: encode (+ fused gram in the last block).
// One WARP per (b,g); 8 warps/block; float4 loads.
// Output written transposed: g_h[b][c][g].
// =====================================================================
__global__ void __launch_bounds__(256) encode_kernel(
    const float* __restrict__ x, const float* __restrict__ y,
    const float* __restrict__ enc_sigma, const float* __restrict__ enc_W,
    const float* __restrict__ enc_b, const float* __restrict__ rho_W,
    const float* __restrict__ rho_b,
    const float* __restrict__ sig_W, const float* __restrict__ sig_b)
{
    int warp = threadIdx.x >> 5, lane = threadIdx.x & 31;

    if (blockIdx.x == (BB * GG) / 8) {
        // ---- gram block: G = sig_W sig_W^T, wb = sig_W @ sig_b, s = b.b
        for (int p = warp * 8; p < warp * 8 + 8; p++) {
            int i = p >> 3, j = p & 7;
            float acc = 0.f;
            for (int k = lane; k < SC; k += 32)
                acc += sig_W[i * SC + k] * sig_W[j * SC + k];
            for (int off = 16; off; off >>= 1)
                acc += __shfl_xor_sync(0xffffffffu, acc, off);
            if (lane == 0) g_G[p] = acc;
        }
        {
            float acc = 0.f;
            for (int k = lane; k < SC; k += 32)
                acc += sig_W[warp * SC + k] * sig_b[k];
            for (int off = 16; off; off >>= 1)
                acc += __shfl_xor_sync(0xffffffffu, acc, off);
            if (lane == 0) g_wb[warp] = acc;
        }
        if (warp == 0) {
            float acc = 0.f;
            for (int k = lane; k < SC; k += 32)
                acc += sig_b[k] * sig_b[k];
            for (int off = 16; off; off >>= 1)
                acc += __shfl_xor_sync(0xffffffffu, acc, off);
            if (lane == 0) g_s[0] = acc;
        }
        return;
    }

    int bg = blockIdx.x * 8 + warp;
    int b  = bg / GG;
    int g  = bg % GG;
    float gv = XMINF + (float)g * STEPF;

    float es0 = enc_sigma[0], es1 = enc_sigma[1];
    float s0 = __expf(es0);  float c0 = -0.5f / (s0 * s0);
    bool same = (es0 == es1);
    float c1 = c0;
    if (!same) { float s1 = __expf(es1); c1 = -0.5f / (s1 * s1); }

    const float4* xb = (const float4*)(x + b * NN);
    const float4* yb = (const float4*)(y + b * NN);

    float f0 = 0.f, f1 = 0.f;
    if (same) {
        #pragma unroll 4
        for (int n = lane; n < NN / 4; n += 32) {
            float4 xv = xb[n], yv = yb[n];
            float dx;
            dx = xv.x - gv; { float e = __expf(c0 * dx * dx); f0 += e; f1 += yv.x * e; }
            dx = xv.y - gv; { float e = __expf(c0 * dx * dx); f0 += e; f1 += yv.y * e; }
            dx = xv.z - gv; { float e = __expf(c0 * dx * dx); f0 += e; f1 += yv.z * e; }
            dx = xv.w - gv; { float e = __expf(c0 * dx * dx); f0 += e; f1 += yv.w * e; }
        }
    } else {
        #pragma unroll 4
        for (int n = lane; n < NN / 4; n += 32) {
            float4 xv = xb[n], yv = yb[n];
            float dx, d;
            dx = xv.x - gv; d = dx * dx; f0 += __expf(c0 * d); f1 += yv.x * __expf(c1 * d);
            dx = xv.y - gv; d = dx * dx; f0 += __expf(c0 * d); f1 += yv.y * __expf(c1 * d);
            dx = xv.z - gv; d = dx * dx; f0 += __expf(c0 * d); f1 += yv.z * __expf(c1 * d);
            dx = xv.w - gv; d = dx * dx; f0 += __expf(c0 * d); f1 += yv.w * __expf(c1 * d);
        }
    }
    for (int off = 16; off; off >>= 1) {
        f0 += __shfl_xor_sync(0xffffffffu, f0, off);
        f1 += __shfl_xor_sync(0xffffffffu, f1, off);
    }
    float F0 = f0;
    float F1 = f1 / (f0 + 1e-8f);

    float hh[RC];
    #pragma unroll
    for (int c = 0; c < RC; c++) {
        float z = F0 * enc_W[c] + F1 * enc_W[RC + c] + enc_b[c];
        hh[c] = 1.f / (1.f + __expf(-z));
    }
    if (lane < RC) {
        int c = lane;
        float acc = rho_b[c];
        #pragma unroll
        for (int j = 0; j < RC; j++) acc += hh[j] * rho_W[j * RC + c];
        g_h[(b * RC + c) * GG + g] = acc;   // transposed layout
    }
}

// =====================================================================
// Kernel 2: project.  One warp per (b,m); 8 warps/block.
// =====================================================================
__global__ void __launch_bounds__(256) project_kernel(
    const float* __restrict__ x_out,
    const float* __restrict__ mean_sigma, const float* __restrict__ mean_W,
    const float* __restrict__ mean_b,
    const float* __restrict__ sig_sigma,
    float* __restrict__ mean_out)
{
    __shared__ float h_sh[RC * GG];    // [c][g]

    int b  = blockIdx.x >> 8;
    int m0 = (blockIdx.x & 255) * 8;
    int tid = threadIdx.x;

    for (int i = tid; i < RC * GG; i += 256)
        h_sh[i] = g_h[b * RC * GG + i];
    __syncthreads();

    int warp = tid >> 5, lane = tid & 31;
    int m = m0 + warp;
    float xo = x_out[b * MM + m];

    // uniformity check on RAW log-sigmas (no exps yet)
    float msv[RC], ssv[RC];
    bool uni = true;
    #pragma unroll
    for (int c = 0; c < RC; c++) {
        msv[c] = mean_sigma[c];
        ssv[c] = sig_sigma[c];
        uni = uni && (msv[c] == msv[0]) && (ssv[c] == msv[0]);
    }

    float pm[RC] = {}, ps[RC] = {};
    if (uni) {
        float s = __expf(msv[0]);
        float coef = -0.5f / (s * s);
        #pragma unroll 1
        for (int g = lane; g < GG; g += 32) {
            float gv = XMINF + (float)g * STEPF;
            float dd = gv - xo; dd *= dd;
            float e = __expf(coef * dd);
            #pragma unroll
            for (int c = 0; c < RC; c++)
                pm[c] += h_sh[c * GG + g] * e;
        }
        #pragma unroll
        for (int c = 0; c < RC; c++) ps[c] = pm[c];
    } else {
        float mc[RC], scf[RC];
        #pragma unroll
        for (int c = 0; c < RC; c++) {
            float s = __expf(msv[c]); mc[c]  = -0.5f / (s * s);
            s       = __expf(ssv[c]); scf[c] = -0.5f / (s * s);
        }
        #pragma unroll 1
        for (int g = lane; g < GG; g += 32) {
            float gv = XMINF + (float)g * STEPF;
            float dd = gv - xo; dd *= dd;
            #pragma unroll
            for (int c = 0; c < RC; c++) {
                float hv = h_sh[c * GG + g];
                pm[c] += hv * __expf(mc[c]  * dd);
                ps[c] += hv * __expf(scf[c] * dd);
            }
        }
    }
    #pragma unroll
    for (int c = 0; c < RC; c++) {
        for (int off = 16; off; off >>= 1) {
            pm[c] += __shfl_xor_sync(0xffffffffu, pm[c], off);
            ps[c] += __shfl_xor_sync(0xffffffffu, ps[c], off);
        }
    }
    size_t base = (size_t)(b * MM + m) * RC;
    if (lane < RC) {
        int c = lane;
        g_P[base + c] = ps[c];
        float qc = 0.f;
        #pragma unroll
        for (int j = 0; j < RC; j++) qc = fmaf(g_G[c * RC + j], ps[j], qc);
        g_Q[base + c] = qc;
    } else if (lane == 8) {
        float uacc = 0.f;
        #pragma unroll
        for (int c = 0; c < RC; c++) uacc = fmaf(ps[c], g_wb[c], uacc);
        g_u[b * MM + m] = uacc;
    } else if (lane == 9) {
        float mv = mean_b[0];
        #pragma unroll
        for (int c = 0; c < RC; c++) mv = fmaf(pm[c], mean_W[c], mv);
        mean_out[b * MM + m] = mv;
    }
}

// =====================================================================
// Kernel 3: cov[b,m,n] = Q[b,m].P[b,n] + (u[m]+s) + u[n]  (+noise diag)
// 64x64 tile / block, 256 threads (16x16), 4x4 per thread.
// Q stored duplicated {q,q} in shared -> packed fma.rn.f32x2 math,
// conflict-free vectorized LDS.
// =====================================================================
__global__ void __launch_bounds__(256) cov_kernel(
    float* __restrict__ cov, const float* __restrict__ noise_scale)
{
    int b  = blockIdx.y;
    int tm = blockIdx.x >> 5;
    int tn = blockIdx.x & 31;

    __shared__ float QsD[RC][128];     // [k][2*m] duplicated pairs {q,q}
    __shared__ float PsT[RC][64];      // [k][m]
    __shared__ float UmS[64], UnS[64]; // UmS includes +s

    int tid = threadIdx.x;
    int rowBase = tm * 64, colBase = tn * 64;

    float sconst = g_s[0];

    if (tid < 128) {
        int r = tid >> 1, q4 = (tid & 1) * 4;
        float4 v = *(const float4*)(g_Q + (size_t)(b * MM + rowBase + r) * RC + q4);
        float2* d0 = (float2*)&QsD[q4 + 0][2 * r];
        float2* d1 = (float2*)&QsD[q4 + 1][2 * r];
        float2* d2 = (float2*)&QsD[q4 + 2][2 * r];
        float2* d3 = (float2*)&QsD[q4 + 3][2 * r];
        *d0 = make_float2(v.x, v.x);
        *d1 = make_float2(v.y, v.y);
        *d2 = make_float2(v.z, v.z);
        *d3 = make_float2(v.w, v.w);
    } else {
        int t = tid - 128;
        int r = t >> 1, q4 = (t & 1) * 4;
        float4 v = *(const float4*)(g_P + (size_t)(b * MM + colBase + r) * RC + q4);
        PsT[q4 + 0][r] = v.x;
        PsT[q4 + 1][r] = v.y;
        PsT[q4 + 2][r] = v.z;
        PsT[q4 + 3][r] = v.w;
    }
    if (tid < 64)       UmS[tid]      = g_u[b * MM + rowBase + tid] + sconst;
    else if (tid < 128) UnS[tid - 64] = g_u[b * MM + colBase + tid - 64];
    __syncthreads();

    int tx = tid & 15, ty = tid >> 4;

    unsigned long long acc[4][2];
    #pragma unroll
    for (int i = 0; i < 4; i++) { acc[i][0] = 0ull; acc[i][1] = 0ull; }

    #pragma unroll
    for (int k = 0; k < RC; k++) {
        // q pairs {q_i, q_i} for i = 0..3  (broadcast LDS.128)
        ulonglong2 qq01 = *(const ulonglong2*)&QsD[k][8 * ty];
        ulonglong2 qq23 = *(const ulonglong2*)&QsD[k][8 * ty + 4];
        // p pairs {p0,p1},{p2,p3}          (conflict-free LDS.128)
        ulonglong2 pp   = *(const ulonglong2*)&PsT[k][4 * tx];

        FMA_F32X2(acc[0][0], qq01.x, pp.x, acc[0][0]);
        FMA_F32X2(acc[0][1], qq01.x, pp.y, acc[0][1]);
        FMA_F32X2(acc[1][0], qq01.y, pp.x, acc[1][0]);
        FMA_F32X2(acc[1][1], qq01.y, pp.y, acc[1][1]);
        FMA_F32X2(acc[2][0], qq23.x, pp.x, acc[2][0]);
        FMA_F32X2(acc[2][1], qq23.x, pp.y, acc[2][1]);
        FMA_F32X2(acc[3][0], qq23.y, pp.x, acc[3][0]);
        FMA_F32X2(acc[3][1], qq23.y, pp.y, acc[3][1]);
    }

    float noisev = __expf(noise_scale[0]);
    bool diag = (tm == tn) && (tx == ty);

    float un0 = UnS[tx * 4 + 0], un1 = UnS[tx * 4 + 1];
    float un2 = UnS[tx * 4 + 2], un3 = UnS[tx * 4 + 3];

    float* C = cov + (size_t)b * MM * MM;
    #pragma unroll
    for (int i = 0; i < 4; i++) {
        float ums = UmS[ty * 4 + i];
        float o0, o1, o2, o3;
        UNPACK_F32X2(o0, o1, acc[i][0]);
        UNPACK_F32X2(o2, o3, acc[i][1]);
        o0 += ums + un0; o1 += ums + un1;
        o2 += ums + un2; o3 += ums + un3;
        if (diag) {
            if (i == 0) o0 += noisev;
            if (i == 1) o1 += noisev;
            if (i == 2) o2 += noisev;
            if (i == 3) o3 += noisev;
        }
        int r = rowBase + ty * 4 + i;
        *(float4*)(C + (size_t)r * MM + colBase + tx * 4) =
            make_float4(o0, o1, o2, o3);
    }
}

// =====================================================================
// launch
// =====================================================================
extern "C" void kernel_launch(void* const* d_in, const int* in_sizes, int n_in,
                              void* d_out, int out_size)
{
    const float* x          = (const float*)d_in[0];
    const float* y          = (const float*)d_in[1];
    const float* x_out      = (const float*)d_in[2];
    const float* enc_sigma  = (const float*)d_in[3];
    const float* enc_W      = (const float*)d_in[4];
    const float* enc_b      = (const float*)d_in[5];
    const float* rho_W      = (const float*)d_in[6];
    const float* rho_b      = (const float*)d_in[7];
    const float* mean_sigma = (const float*)d_in[8];
    const float* mean_W     = (const float*)d_in[9];
    const float* mean_b     = (const float*)d_in[10];
    const float* sig_sigma  = (const float*)d_in[11];
    const float* sig_W      = (const float*)d_in[12];
    const float* sig_b      = (const float*)d_in[13];
    const float* noise      = (const float*)d_in[14];

    float* out      = (float*)d_out;
    float* mean_out = out;                    // (8, 2048, 1)
    float* cov_out  = out + BB * MM;          // (8, 2048, 2048)

    encode_kernel<<<BB * GG / 8 + 1, 256>>>(x, y, enc_sigma, enc_W, enc_b,
                                            rho_W, rho_b, sig_W, sig_b);

    project_kernel<<<BB * 256, 256>>>(x_out, mean_sigma, mean_W, mean_b,
                                      sig_sigma, mean_out);

    dim3 cgrid(1024, BB);   // 32x32 tiles of 64x64
    cov_kernel<<<cgrid, 256>>>(cov_out, noise);
}

// round 5
// speedup vs baseline: 16.8028x; 1.2273x over previous
#include <cuda_runtime.h>
#include <math.h>

// ---------------- problem constants ----------------
#define BB   8
#define NN   2048
#define MM   2048
#define GG   544          // NUM_GRID
#define RC   8            // RHO_C
#define SC   1024         // SIGMA_CH
#define XMINF (-2.1f)
#define STEPF ((float)(4.2 / 543.0))
#define CUT_T 25.0f       // exp threshold: drop terms below e^-25 of peak

// ---------------- scratch (device globals) ----------------
__device__ float g_h[BB * RC * GG];          // h transposed: [b][c][g]
__device__ float g_P[BB * MM * RC];          // ps[b,m,c]
__device__ float g_Q[BB * MM * RC];          // (G @ ps)[b,m,c]
__device__ float g_u[BB * MM];               // ps . (W b)
__device__ float g_G[RC * RC];               // sig_W sig_W^T
__device__ float g_wb[RC];                   // sig_W @ sig_b
__device__ float g_s[1];                     // sig_b . sig_b
__device__ float g_xs[BB * NN];              // bucket-sorted x
__device__ float g_ys[BB * NN];              // bucket-sorted y
__device__ int   g_start[BB * (GG + 1)];     // bucket starts per batch

// ---------------- packed f32x2 helpers (Blackwell) ----------------
#define FMA_F32X2(d, a, b, c) \
    asm("fma.rn.f32x2 %0, %1, %2, %3;" : "=l"(d) : "l"(a), "l"(b), "l"(c))
#define UNPACK_F32X2(lo, hi, v) \
    asm("mov.b64 {%0, %1}, %2;" : "=f"(lo), "=f"(hi) : "l"(v))

// window half-width in grid cells for gaussian coef c (negative)
__device__ __forceinline__ int windowW(float negc)   // negc = |c|
{
    float dxmax = sqrtf(CUT_T / fmaxf(negc, 1e-30f));
    float wf = dxmax / STEPF + 2.0f;
    return (wf > (float)GG) ? GG : (int)wf;
}

// =====================================================================
// Kernel A: bucket sort per batch (blocks 0..7) + gram (block 8).
// =====================================================================
__global__ void __launch_bounds__(576) bucket_kernel(
    const float* __restrict__ x, const float* __restrict__ y,
    const float* __restrict__ sig_W, const float* __restrict__ sig_b)
{
    int tid = threadIdx.x;
    int warp = tid >> 5, lane = tid & 31;

    if (blockIdx.x == BB) {
        // ---- gram block: G = sig_W sig_W^T, wb = sig_W @ sig_b, s = b.b
        if (warp < 8) {
            for (int p = warp * 8; p < warp * 8 + 8; p++) {
                int i = p >> 3, j = p & 7;
                float acc = 0.f;
                for (int k = lane; k < SC; k += 32)
                    acc += sig_W[i * SC + k] * sig_W[j * SC + k];
                for (int off = 16; off; off >>= 1)
                    acc += __shfl_xor_sync(0xffffffffu, acc, off);
                if (lane == 0) g_G[p] = acc;
            }
            float acc = 0.f;
            for (int k = lane; k < SC; k += 32)
                acc += sig_W[warp * SC + k] * sig_b[k];
            for (int off = 16; off; off >>= 1)
                acc += __shfl_xor_sync(0xffffffffu, acc, off);
            if (lane == 0) g_wb[warp] = acc;
            if (warp == 0) {
                float a2 = 0.f;
                for (int k = lane; k < SC; k += 32)
                    a2 += sig_b[k] * sig_b[k];
                for (int off = 16; off; off >>= 1)
                    a2 += __shfl_xor_sync(0xffffffffu, a2, off);
                if (lane == 0) g_s[0] = a2;
            }
        }
        return;
    }

    int b = blockIdx.x;
    __shared__ int cnt[GG + 1];
    __shared__ int ofs[GG + 1];

    for (int i = tid; i < GG + 1; i += 576) cnt[i] = 0;
    __syncthreads();

    float px[4], py[4];
    int pc[4], np = 0;
    for (int n = tid; n < NN; n += 576) {
        float xv = x[b * NN + n], yv = y[b * NN + n];
        float cf = (xv - XMINF) / STEPF + 0.5f;
        int cell = (int)cf;
        cell = min(max(cell, 0), GG - 1);
        px[np] = xv; py[np] = yv; pc[np] = cell; np++;
        atomicAdd(&cnt[cell], 1);
    }
    __syncthreads();

    // Kogge-Stone inclusive scan over GG+1 entries
    for (int off = 1; off < GG + 1; off <<= 1) {
        int v = 0;
        if (tid < GG + 1) {
            v = cnt[tid];
            if (tid >= off) v += cnt[tid - off];
        }
        __syncthreads();
        if (tid < GG + 1) cnt[tid] = v;
        __syncthreads();
    }
    if (tid < GG + 1) {
        int s = (tid == 0) ? 0 : cnt[tid - 1];   // exclusive
        ofs[tid] = s;
        g_start[b * (GG + 1) + tid] = s;
    }
    __syncthreads();

    for (int i = 0; i < np; i++) {
        int pos = atomicAdd(&ofs[pc[i]], 1);
        g_xs[b * NN + pos] = px[i];
        g_ys[b * NN + pos] = py[i];
    }
}

// =====================================================================
// Kernel B: encode.  One WARP per (b,g), windowed over bucketed points.
// =====================================================================
__global__ void __launch_bounds__(256) encode_kernel(
    const float* __restrict__ enc_sigma, const float* __restrict__ enc_W,
    const float* __restrict__ enc_b, const float* __restrict__ rho_W,
    const float* __restrict__ rho_b)
{
    int warp = threadIdx.x >> 5, lane = threadIdx.x & 31;
    int bg = blockIdx.x * 8 + warp;
    int b  = bg / GG;
    int g  = bg % GG;
    float gv = XMINF + (float)g * STEPF;

    float es0 = enc_sigma[0], es1 = enc_sigma[1];
    float s0 = __expf(es0);  float c0 = -0.5f / (s0 * s0);
    bool same = (es0 == es1);
    float c1 = c0;
    int W = windowW(-c0);
    if (!same) {
        float s1 = __expf(es1);
        c1 = -0.5f / (s1 * s1);
        W = max(W, windowW(-c1));
    }
    int glo = max(0, g - W), ghi = min(GG - 1, g + W);
    int lo = g_start[b * (GG + 1) + glo];
    int hi = g_start[b * (GG + 1) + ghi + 1];

    float f0 = 0.f, f1 = 0.f;
    if (same) {
        for (int n = lo + lane; n < hi; n += 32) {
            float dx = g_xs[b * NN + n] - gv;
            float e  = __expf(c0 * dx * dx);
            f0 += e;
            f1 += g_ys[b * NN + n] * e;
        }
    } else {
        for (int n = lo + lane; n < hi; n += 32) {
            float dx = g_xs[b * NN + n] - gv;
            float d  = dx * dx;
            f0 += __expf(c0 * d);
            f1 += g_ys[b * NN + n] * __expf(c1 * d);
        }
    }
    for (int off = 16; off; off >>= 1) {
        f0 += __shfl_xor_sync(0xffffffffu, f0, off);
        f1 += __shfl_xor_sync(0xffffffffu, f1, off);
    }
    float F0 = f0;
    float F1 = f1 / (f0 + 1e-8f);

    float hh[RC];
    #pragma unroll
    for (int c = 0; c < RC; c++) {
        float z = F0 * enc_W[c] + F1 * enc_W[RC + c] + enc_b[c];
        hh[c] = 1.f / (1.f + __expf(-z));
    }
    if (lane < RC) {
        int c = lane;
        float acc = rho_b[c];
        #pragma unroll
        for (int j = 0; j < RC; j++) acc += hh[j] * rho_W[j * RC + c];
        g_h[(b * RC + c) * GG + g] = acc;   // transposed layout
    }
}

// =====================================================================
// Kernel C: project.  One 8-lane GROUP per (b,m); 32 m per block.
// Windowed g-loop.
// =====================================================================
__global__ void __launch_bounds__(256) project_kernel(
    const float* __restrict__ x_out,
    const float* __restrict__ mean_sigma, const float* __restrict__ mean_W,
    const float* __restrict__ mean_b,
    const float* __restrict__ sig_sigma,
    float* __restrict__ mean_out)
{
    __shared__ float h_sh[RC * GG];    // [c][g]

    int b  = blockIdx.x >> 6;          // 64 blocks per batch
    int m0 = (blockIdx.x & 63) * 32;
    int tid = threadIdx.x;

    for (int i = tid; i < RC * GG; i += 256)
        h_sh[i] = g_h[b * RC * GG + i];
    __syncthreads();

    int gid   = tid >> 3;              // 0..31 : which m
    int lane8 = tid & 7;
    int m = m0 + gid;
    float xo = x_out[b * MM + m];

    // uniformity check on raw log-sigmas
    bool uni = true;
    float ms0 = mean_sigma[0];
    float maxls = ms0;
    #pragma unroll
    for (int c = 0; c < RC; c++) {
        float mv = mean_sigma[c], sv = sig_sigma[c];
        uni = uni && (mv == ms0) && (sv == ms0);
        maxls = fmaxf(maxls, fmaxf(mv, sv));
    }

    // window from the largest sigma (smallest |coef|)
    float smax = __expf(maxls);
    float dxmax = smax * sqrtf(2.0f * CUT_T);
    int glo, ghi;
    if (dxmax > 4.2f) { glo = 0; ghi = GG - 1; }
    else {
        glo = max(0, (int)((xo - XMINF - dxmax) / STEPF));
        ghi = min(GG - 1, (int)((xo - XMINF + dxmax) / STEPF) + 1);
    }

    float pm[RC] = {}, ps[RC] = {};
    if (uni) {
        float s = __expf(ms0);
        float coef = -0.5f / (s * s);
        for (int g = glo + lane8; g <= ghi; g += 8) {
            float gv = XMINF + (float)g * STEPF;
            float dd = gv - xo; dd *= dd;
            float e = __expf(coef * dd);
            #pragma unroll
            for (int c = 0; c < RC; c++)
                pm[c] += h_sh[c * GG + g] * e;
        }
        #pragma unroll
        for (int c = 0; c < RC; c++) ps[c] = pm[c];
    } else {
        float mc[RC], scf[RC];
        #pragma unroll
        for (int c = 0; c < RC; c++) {
            float s = __expf(mean_sigma[c]); mc[c]  = -0.5f / (s * s);
            s       = __expf(sig_sigma[c]);  scf[c] = -0.5f / (s * s);
        }
        for (int g = glo + lane8; g <= ghi; g += 8) {
            float gv = XMINF + (float)g * STEPF;
            float dd = gv - xo; dd *= dd;
            #pragma unroll
            for (int c = 0; c < RC; c++) {
                float hv = h_sh[c * GG + g];
                pm[c] += hv * __expf(mc[c]  * dd);
                ps[c] += hv * __expf(scf[c] * dd);
            }
        }
    }
    // reduce within 8-lane group
    #pragma unroll
    for (int c = 0; c < RC; c++) {
        #pragma unroll
        for (int off = 4; off; off >>= 1) {
            pm[c] += __shfl_xor_sync(0xffffffffu, pm[c], off);
            ps[c] += __shfl_xor_sync(0xffffffffu, ps[c], off);
        }
    }

    size_t base = (size_t)(b * MM + m) * RC;
    {
        int c = lane8;
        g_P[base + c] = ps[c];
        float qc = 0.f;
        #pragma unroll
        for (int j = 0; j < RC; j++) qc = fmaf(g_G[c * RC + j], ps[j], qc);
        g_Q[base + c] = qc;
    }
    if (lane8 == 0) {
        float uacc = 0.f;
        #pragma unroll
        for (int c = 0; c < RC; c++) uacc = fmaf(ps[c], g_wb[c], uacc);
        g_u[b * MM + m] = uacc;
    } else if (lane8 == 1) {
        float mv = mean_b[0];
        #pragma unroll
        for (int c = 0; c < RC; c++) mv = fmaf(pm[c], mean_W[c], mv);
        mean_out[b * MM + m] = mv;
    }
}

// =====================================================================
// Kernel D: cov[b,m,n] = Q[b,m].P[b,n] + (u[m]+s) + u[n]  (+noise diag)
// 64x64 tile / block, 256 threads (16x16), 4x4 per thread, f32x2 math.
// =====================================================================
__global__ void __launch_bounds__(256) cov_kernel(
    float* __restrict__ cov, const float* __restrict__ noise_scale)
{
    int b  = blockIdx.y;
    int tm = blockIdx.x >> 5;
    int tn = blockIdx.x & 31;

    __shared__ float QsD[RC][128];     // [k][2*m] duplicated pairs {q,q}
    __shared__ float PsT[RC][64];      // [k][m]
    __shared__ float UmS[64], UnS[64]; // UmS includes +s

    int tid = threadIdx.x;
    int rowBase = tm * 64, colBase = tn * 64;

    float sconst = g_s[0];

    if (tid < 128) {
        int r = tid >> 1, q4 = (tid & 1) * 4;
        float4 v = *(const float4*)(g_Q + (size_t)(b * MM + rowBase + r) * RC + q4);
        *(float2*)&QsD[q4 + 0][2 * r] = make_float2(v.x, v.x);
        *(float2*)&QsD[q4 + 1][2 * r] = make_float2(v.y, v.y);
        *(float2*)&QsD[q4 + 2][2 * r] = make_float2(v.z, v.z);
        *(float2*)&QsD[q4 + 3][2 * r] = make_float2(v.w, v.w);
    } else {
        int t = tid - 128;
        int r = t >> 1, q4 = (t & 1) * 4;
        float4 v = *(const float4*)(g_P + (size_t)(b * MM + colBase + r) * RC + q4);
        PsT[q4 + 0][r] = v.x;
        PsT[q4 + 1][r] = v.y;
        PsT[q4 + 2][r] = v.z;
        PsT[q4 + 3][r] = v.w;
    }
    if (tid < 64)       UmS[tid]      = g_u[b * MM + rowBase + tid] + sconst;
    else if (tid < 128) UnS[tid - 64] = g_u[b * MM + colBase + tid - 64];
    __syncthreads();

    int tx = tid & 15, ty = tid >> 4;

    unsigned long long acc[4][2];
    #pragma unroll
    for (int i = 0; i < 4; i++) { acc[i][0] = 0ull; acc[i][1] = 0ull; }

    #pragma unroll
    for (int k = 0; k < RC; k++) {
        ulonglong2 qq01 = *(const ulonglong2*)&QsD[k][8 * ty];
        ulonglong2 qq23 = *(const ulonglong2*)&QsD[k][8 * ty + 4];
        ulonglong2 pp   = *(const ulonglong2*)&PsT[k][4 * tx];

        FMA_F32X2(acc[0][0], qq01.x, pp.x, acc[0][0]);
        FMA_F32X2(acc[0][1], qq01.x, pp.y, acc[0][1]);
        FMA_F32X2(acc[1][0], qq01.y, pp.x, acc[1][0]);
        FMA_F32X2(acc[1][1], qq01.y, pp.y, acc[1][1]);
        FMA_F32X2(acc[2][0], qq23.x, pp.x, acc[2][0]);
        FMA_F32X2(acc[2][1], qq23.x, pp.y, acc[2][1]);
        FMA_F32X2(acc[3][0], qq23.y, pp.x, acc[3][0]);
        FMA_F32X2(acc[3][1], qq23.y, pp.y, acc[3][1]);
    }

    float noisev = __expf(noise_scale[0]);
    bool diag = (tm == tn) && (tx == ty);

    float un0 = UnS[tx * 4 + 0], un1 = UnS[tx * 4 + 1];
    float un2 = UnS[tx * 4 + 2], un3 = UnS[tx * 4 + 3];

    float* C = cov + (size_t)b * MM * MM;
    #pragma unroll
    for (int i = 0; i < 4; i++) {
        float ums = UmS[ty * 4 + i];
        float o0, o1, o2, o3;
        UNPACK_F32X2(o0, o1, acc[i][0]);
        UNPACK_F32X2(o2, o3, acc[i][1]);
        o0 += ums + un0; o1 += ums + un1;
        o2 += ums + un2; o3 += ums + un3;
        if (diag) {
            if (i == 0) o0 += noisev;
            if (i == 1) o1 += noisev;
            if (i == 2) o2 += noisev;
            if (i == 3) o3 += noisev;
        }
        int r = rowBase + ty * 4 + i;
        *(float4*)(C + (size_t)r * MM + colBase + tx * 4) =
            make_float4(o0, o1, o2, o3);
    }
}

// =====================================================================
// launch
// =====================================================================
extern "C" void kernel_launch(void* const* d_in, const int* in_sizes, int n_in,
                              void* d_out, int out_size)
{
    const float* x          = (const float*)d_in[0];
    const float* y          = (const float*)d_in[1];
    const float* x_out      = (const float*)d_in[2];
    const float* enc_sigma  = (const float*)d_in[3];
    const float* enc_W      = (const float*)d_in[4];
    const float* enc_b      = (const float*)d_in[5];
    const float* rho_W      = (const float*)d_in[6];
    const float* rho_b      = (const float*)d_in[7];
    const float* mean_sigma = (const float*)d_in[8];
    const float* mean_W     = (const float*)d_in[9];
    const float* mean_b     = (const float*)d_in[10];
    const float* sig_sigma  = (const float*)d_in[11];
    const float* sig_W      = (const float*)d_in[12];
    const float* sig_b      = (const float*)d_in[13];
    const float* noise      = (const float*)d_in[14];

    float* out      = (float*)d_out;
    float* mean_out = out;                    // (8, 2048, 1)
    float* cov_out  = out + BB * MM;          // (8, 2048, 2048)

    bucket_kernel<<<BB + 1, 576>>>(x, y, sig_W, sig_b);

    encode_kernel<<<BB * GG / 8, 256>>>(enc_sigma, enc_W, enc_b, rho_W, rho_b);

    project_kernel<<<BB * 64, 256>>>(x_out, mean_sigma, mean_W, mean_b,
                                     sig_sigma, mean_out);

    dim3 cgrid(1024, BB);   // 32x32 tiles of 64x64
    cov_kernel<<<cgrid, 256>>>(cov_out, noise);
}